// round 4
// baseline (speedup 1.0000x reference)
#include <cuda_runtime.h>
#include <cuda_fp16.h>
#include <cstdint>

#define N_NODE 50000
#define N_EDGE 800000
#define D_FEAT 64
#define DEPTH  3
#define M_TERMS 11
#define NF (N_NODE * D_FEAT)   // 3,200,000
#define SCAN_BS 1024
#define NBLK_SCAN ((N_NODE + SCAN_BS - 1) / SCAN_BS)   // 49

// ---------------- scratch (device globals; no allocs allowed) ----------------
__device__ float  g_y32[2 * NF];          // S^1 x, S^2 x  (fp32, for epilogue)
__device__ __half g_yh[2 * NF];           // fp16 copies (for next gather)
__device__ __half g_xh[NF];               // fp16 copy of x
__device__ float  g_dinv[N_NODE];
__device__ int    g_cnt[N_NODE];          // degree counts, then fill cursors
__device__ int    g_rowptr[N_NODE + 1];
__device__ int    g_scanval[64];          // chained-scan running totals
__device__ int    g_flag[64];             // chained-scan ready flags
__device__ int2   g_epk[N_EDGE];          // packed (col, val-bits) in CSR order
__device__ float  g_C[16];                // C[L][k] combination coefficients

// ---------------- setup ----------------
__global__ void k_init() {
    int i = blockIdx.x * blockDim.x + threadIdx.x;
    if (i < N_NODE) g_cnt[i] = 0;
    if (i < 64) g_flag[i] = 0;
}

// Fused: degree histogram (800K edges) + x -> fp16 conversion (800K float4 chunks)
__global__ void k_deg_xtoh(const int* __restrict__ row, const float* __restrict__ x) {
    int e = blockIdx.x * blockDim.x + threadIdx.x;
    if (e >= N_EDGE) return;
    atomicAdd(&g_cnt[row[e]], 1);
    float4 v = __ldg((const float4*)(x + (size_t)e * 4));
    __half2 h0 = __floats2half2_rn(v.x, v.y);
    __half2 h1 = __floats2half2_rn(v.z, v.w);
    *(uint2*)(g_xh + (size_t)e * 4) = make_uint2(*(uint32_t*)&h0, *(uint32_t*)&h1);
}

// Single-kernel chained scan: rowptr (exclusive), dinv, cursor reset.
__global__ void __launch_bounds__(SCAN_BS) k_scan() {
    __shared__ int warp_sums[32];
    __shared__ int s_prefix;
    int b = blockIdx.x;
    int i = b * SCAN_BS + threadIdx.x;
    int lane = threadIdx.x & 31, wid = threadIdx.x >> 5;
    int v = (i < N_NODE) ? g_cnt[i] : 0;

    // warp inclusive scan
    int incl = v;
#pragma unroll
    for (int o = 1; o < 32; o <<= 1) {
        int t = __shfl_up_sync(0xFFFFFFFFu, incl, o);
        if (lane >= o) incl += t;
    }
    if (lane == 31) warp_sums[wid] = incl;
    __syncthreads();
    if (wid == 0) {
        int s = warp_sums[lane];
#pragma unroll
        for (int o = 1; o < 32; o <<= 1) {
            int t = __shfl_up_sync(0xFFFFFFFFu, s, o);
            if (lane >= o) s += t;
        }
        warp_sums[lane] = s;
    }
    __syncthreads();
    int block_excl = (wid > 0) ? warp_sums[wid - 1] : 0;
    int incl_block = incl + block_excl;
    int block_total = warp_sums[31];

    if (threadIdx.x == 0) {
        int prefix = 0;
        if (b > 0) {
            while (atomicAdd(&g_flag[b - 1], 0) == 0) { }
            __threadfence();
            prefix = g_scanval[b - 1];
        }
        g_scanval[b] = prefix + block_total;
        __threadfence();
        atomicExch(&g_flag[b], 1);
        s_prefix = prefix;
    }
    __syncthreads();

    if (i < N_NODE) {
        g_rowptr[i] = s_prefix + incl_block - v;     // exclusive prefix
        float d = (v == 0) ? 1.0f : (float)v;
        g_dinv[i] = rsqrtf(d);
        g_cnt[i] = 0;                                 // reset as fill cursor
    }
    if (i == 0) g_rowptr[N_NODE] = N_EDGE;
}

// Fill CSR: packed (col, normalized val) per edge, grouped by row.
__global__ void k_fill(const int* __restrict__ row, const int* __restrict__ col,
                       const float* __restrict__ ea) {
    int e = blockIdx.x * blockDim.x + threadIdx.x;
    if (e >= N_EDGE) return;
    int r = row[e];
    int c = col[e];
    float v = __ldg(&g_dinv[r]) * ea[e] * __ldg(&g_dinv[c]);
    int pos = g_rowptr[r] + atomicAdd(&g_cnt[r], 1);
    g_epk[pos] = make_int2(c, __float_as_int(v));
}

// ---------------- CSR SpMM: 8 threads per node, 8 feats each ----------------
// gathers fp16 (128 B/row), accumulates fp32, dual-stores fp32 + fp16
__global__ void k_spmm(const __half* __restrict__ xin,
                       float* __restrict__ y32, __half* __restrict__ y16) {
    int t = blockIdx.x * blockDim.x + threadIdx.x;
    int n = t >> 3;
    if (n >= N_NODE) return;
    int c = (t & 7) << 3;
    int s = __ldg(&g_rowptr[n]);
    int e = __ldg(&g_rowptr[n + 1]);

    float a0 = 0.f, a1 = 0.f, a2 = 0.f, a3 = 0.f;
    float a4 = 0.f, a5 = 0.f, a6 = 0.f, a7 = 0.f;

    for (int i = s; i < e; i++) {
        int2 pk = __ldg(&g_epk[i]);
        float v = __int_as_float(pk.y);
        uint4 raw = __ldg((const uint4*)(xin + (size_t)pk.x * D_FEAT + c));
        float2 f0 = __half22float2(*(__half2*)&raw.x);
        float2 f1 = __half22float2(*(__half2*)&raw.y);
        float2 f2 = __half22float2(*(__half2*)&raw.z);
        float2 f3 = __half22float2(*(__half2*)&raw.w);
        a0 = fmaf(v, f0.x, a0); a1 = fmaf(v, f0.y, a1);
        a2 = fmaf(v, f1.x, a2); a3 = fmaf(v, f1.y, a3);
        a4 = fmaf(v, f2.x, a4); a5 = fmaf(v, f2.y, a5);
        a6 = fmaf(v, f3.x, a6); a7 = fmaf(v, f3.y, a7);
    }

    size_t off = (size_t)n * D_FEAT + c;
    *(float4*)(y32 + off)     = make_float4(a0, a1, a2, a3);
    *(float4*)(y32 + off + 4) = make_float4(a4, a5, a6, a7);

    __half2 o0 = __floats2half2_rn(a0, a1);
    __half2 o1 = __floats2half2_rn(a2, a3);
    __half2 o2 = __floats2half2_rn(a4, a5);
    __half2 o3 = __floats2half2_rn(a6, a7);
    *(uint4*)(y16 + off) = make_uint4(*(uint32_t*)&o0, *(uint32_t*)&o1,
                                      *(uint32_t*)&o2, *(uint32_t*)&o3);
}

// ---------------- fused SpMM3 + epilogue ----------------
// y3 = S*y2 computed in registers; out[n,L,c] = C[L][0] x + C[L][1] y1 + C[L][2] y2 + C[L][3] y3
__global__ void k_spmm_out(const __half* __restrict__ y2h,
                           const float* __restrict__ x, float* __restrict__ out) {
    int t = blockIdx.x * blockDim.x + threadIdx.x;
    int n = t >> 3;
    if (n >= N_NODE) return;
    int c = (t & 7) << 3;
    int s = __ldg(&g_rowptr[n]);
    int e = __ldg(&g_rowptr[n + 1]);

    float a0 = 0.f, a1 = 0.f, a2 = 0.f, a3 = 0.f;
    float a4 = 0.f, a5 = 0.f, a6 = 0.f, a7 = 0.f;

    for (int i = s; i < e; i++) {
        int2 pk = __ldg(&g_epk[i]);
        float v = __int_as_float(pk.y);
        uint4 raw = __ldg((const uint4*)(y2h + (size_t)pk.x * D_FEAT + c));
        float2 f0 = __half22float2(*(__half2*)&raw.x);
        float2 f1 = __half22float2(*(__half2*)&raw.y);
        float2 f2 = __half22float2(*(__half2*)&raw.z);
        float2 f3 = __half22float2(*(__half2*)&raw.w);
        a0 = fmaf(v, f0.x, a0); a1 = fmaf(v, f0.y, a1);
        a2 = fmaf(v, f1.x, a2); a3 = fmaf(v, f1.y, a3);
        a4 = fmaf(v, f2.x, a4); a5 = fmaf(v, f2.y, a5);
        a6 = fmaf(v, f3.x, a6); a7 = fmaf(v, f3.y, a7);
    }

    size_t off = (size_t)n * D_FEAT + c;
    float4 x0 = __ldg((const float4*)(x + off));
    float4 x1 = __ldg((const float4*)(x + off + 4));
    float4 p0 = *(const float4*)(g_y32 + off);
    float4 p1 = *(const float4*)(g_y32 + off + 4);
    float4 q0 = *(const float4*)(g_y32 + (size_t)NF + off);
    float4 q1 = *(const float4*)(g_y32 + (size_t)NF + off + 4);

    float* ob = out + (size_t)n * ((DEPTH + 1) * D_FEAT) + c;
#pragma unroll
    for (int L = 0; L <= DEPTH; L++) {
        float c0 = g_C[L * 4 + 0], c1 = g_C[L * 4 + 1];
        float c2 = g_C[L * 4 + 2], c3 = g_C[L * 4 + 3];
        float4 o;
        o.x = c0 * x0.x + c1 * p0.x + c2 * q0.x + c3 * a0;
        o.y = c0 * x0.y + c1 * p0.y + c2 * q0.y + c3 * a1;
        o.z = c0 * x0.z + c1 * p0.z + c2 * q0.z + c3 * a2;
        o.w = c0 * x0.w + c1 * p0.w + c2 * q0.w + c3 * a3;
        *(float4*)(ob + (size_t)L * D_FEAT) = o;
        float4 u;
        u.x = c0 * x1.x + c1 * p1.x + c2 * q1.x + c3 * a4;
        u.y = c0 * x1.y + c1 * p1.y + c2 * q1.y + c3 * a5;
        u.z = c0 * x1.z + c1 * p1.z + c2 * q1.z + c3 * a6;
        u.w = c0 * x1.w + c1 * p1.w + c2 * q1.w + c3 * a7;
        *(float4*)(ob + (size_t)L * D_FEAT + 4) = u;
    }
}

// ---------------- coefficient collapse (tiny, fp32) ----------------
__global__ void k_coef(const float* __restrict__ alphas, const float* __restrict__ w,
                       const float* __restrict__ aarr, const float* __restrict__ barr) {
    if (blockIdx.x != 0 || threadIdx.x != 0) return;
    const float l = -1.0f, r = 1.0f;
    float C[DEPTH + 1][DEPTH + 1];
    for (int L = 0; L <= DEPTH; L++)
        for (int k = 0; k <= DEPTH; k++) C[L][k] = 0.0f;

    for (int m = 0; m < M_TERMS; m++) {
        float a = aarr[m], b = barr[m], wm = w[m];
        float P[DEPTH + 1][DEPTH + 1];
        for (int L = 0; L <= DEPTH; L++)
            for (int k = 0; k <= DEPTH; k++) P[L][k] = 0.0f;
        P[0][0] = 1.0f;

        float coef1 = (a - b) * 0.5f - (a + b + 2.0f) * 0.5f * (l + r) / (r - l);
        float coef2 = (a + b + 2.0f) / (r - l);
        float al0 = alphas[0 * M_TERMS + m];
        P[1][0] = al0 * coef1;
        P[1][1] = al0 * coef2;

        for (int L = 2; L <= DEPTH; L++) {
            float Lf = (float)L;
            float coef_l     = 2.0f * Lf * (Lf + a + b) * (2.0f * Lf - 2.0f + a + b);
            float coef_lm1_1 = (2.0f * Lf + a + b - 1.0f) * (2.0f * Lf + a + b) * (2.0f * Lf + a + b - 2.0f);
            float coef_lm1_2 = (2.0f * Lf + a + b - 1.0f) * (a * a - b * b);
            float coef_lm2   = 2.0f * (Lf - 1.0f + a) * (Lf - 1.0f + b) * (2.0f * Lf + a + b);
            float alL   = alphas[(L - 1) * M_TERMS + m];
            float alLm1 = alphas[(L - 2) * M_TERMS + m];
            float t1 = alL * (coef_lm1_1 / coef_l);
            float t2 = alL * (coef_lm1_2 / coef_l);
            float t3 = alL * alLm1 * (coef_lm2 / coef_l);
            float t1_2 = t1 * (2.0f / (r - l));
            float t2_2 = t1 * ((r + l) / (r - l)) + t2;
            for (int k = 0; k <= L; k++) {
                float pm1 = (k > 0) ? P[L - 1][k - 1] : 0.0f;
                P[L][k] = t1_2 * pm1 - t2_2 * P[L - 1][k] - t3 * P[L - 2][k];
            }
        }
        for (int L = 0; L <= DEPTH; L++)
            for (int k = 0; k <= L; k++) C[L][k] += wm * P[L][k];
    }
    for (int L = 0; L <= DEPTH; L++)
        for (int k = 0; k <= DEPTH; k++) g_C[L * 4 + k] = C[L][k];
}

// ---------------- launch ----------------
extern "C" void kernel_launch(void* const* d_in, const int* in_sizes, int n_in,
                              void* d_out, int out_size) {
    const float* x      = (const float*)d_in[0];
    const int*   eidx   = (const int*)d_in[1];      // (2, N_EDGE): row then col
    const float* eattr  = (const float*)d_in[2];
    const float* alphas = (const float*)d_in[3];
    const float* w      = (const float*)d_in[4];
    const float* a_arr  = (const float*)d_in[5];
    const float* b_arr  = (const float*)d_in[6];
    float* out = (float*)d_out;

    const int* row = eidx;
    const int* col = eidx + N_EDGE;

    static float*  y32 = nullptr;
    static __half* yh  = nullptr;
    static __half* xh  = nullptr;
    if (!y32) {
        cudaGetSymbolAddress((void**)&y32, g_y32);
        cudaGetSymbolAddress((void**)&yh,  g_yh);
        cudaGetSymbolAddress((void**)&xh,  g_xh);
    }

    const int B = 256;
    k_init<<<(N_NODE + B - 1) / B, B>>>();
    k_deg_xtoh<<<(N_EDGE + B - 1) / B, B>>>(row, x);
    k_scan<<<NBLK_SCAN, SCAN_BS>>>();
    k_fill<<<(N_EDGE + B - 1) / B, B>>>(row, col, eattr);
    k_coef<<<1, 32>>>(alphas, w, a_arr, b_arr);

    const int spmm_blocks = (N_NODE * 8 + B - 1) / B;   // 1563
    k_spmm<<<spmm_blocks, B>>>(xh, y32,      yh);
    k_spmm<<<spmm_blocks, B>>>(yh, y32 + NF, yh + NF);
    k_spmm_out<<<spmm_blocks, B>>>(yh + NF, x, out);
}

// round 7
// speedup vs baseline: 1.0223x; 1.0223x over previous
#include <cuda_runtime.h>
#include <cuda_fp16.h>
#include <cstdint>

#define N_NODE 50000
#define N_EDGE 800000
#define D_FEAT 64
#define DEPTH  3
#define M_TERMS 11
#define NF (N_NODE * D_FEAT)   // 3,200,000
#define SCAN_BS 1024
#define NBLK_SCAN ((N_NODE + SCAN_BS - 1) / SCAN_BS)   // 49

// ---------------- scratch (device globals; zero-initialized at load) ----------------
__device__ float  g_y32[2 * NF];          // S^1 x, S^2 x  (fp32, for epilogue)
__device__ __half g_yh[2 * NF];           // fp16 copies (for next gather)
__device__ __half g_xh[NF];               // fp16 copy of x
__device__ float  g_dinv[N_NODE];
__device__ int    g_cnt[N_NODE];          // degree counts (zero invariant between calls)
__device__ int    g_rowptr[N_NODE + 1];
__device__ int    g_cur[N_NODE];          // fill cursors (re-init by scan each call)
__device__ int    g_scanval[64];          // chained-scan running totals
__device__ int    g_flag[64];             // chained-scan ready flags (reset by k_fill)
__device__ int2   g_epk[N_EDGE];          // packed (col, ea*dinv[col]) in CSR order
__device__ float  g_C[16];                // C[L][k] combination coefficients

// Fused: degree histogram (800K edges) + x -> fp16 conversion (800K float4 chunks)
__global__ void k_deg_xtoh(const int* __restrict__ row, const float* __restrict__ x) {
    int e = blockIdx.x * blockDim.x + threadIdx.x;
    if (e >= N_EDGE) return;
    atomicAdd(&g_cnt[row[e]], 1);
    float4 v = __ldg((const float4*)(x + (size_t)e * 4));
    __half2 h0 = __floats2half2_rn(v.x, v.y);
    __half2 h1 = __floats2half2_rn(v.z, v.w);
    *(uint2*)(g_xh + (size_t)e * 4) = make_uint2(*(uint32_t*)&h0, *(uint32_t*)&h1);
}

// Single-kernel chained scan: rowptr + cursor copy (exclusive), dinv, cnt reset.
__global__ void __launch_bounds__(SCAN_BS) k_scan() {
    __shared__ int warp_sums[32];
    __shared__ int s_prefix;
    int b = blockIdx.x;
    int i = b * SCAN_BS + threadIdx.x;
    int lane = threadIdx.x & 31, wid = threadIdx.x >> 5;
    int v = (i < N_NODE) ? g_cnt[i] : 0;

    int incl = v;
#pragma unroll
    for (int o = 1; o < 32; o <<= 1) {
        int t = __shfl_up_sync(0xFFFFFFFFu, incl, o);
        if (lane >= o) incl += t;
    }
    if (lane == 31) warp_sums[wid] = incl;
    __syncthreads();
    if (wid == 0) {
        int s = warp_sums[lane];
#pragma unroll
        for (int o = 1; o < 32; o <<= 1) {
            int t = __shfl_up_sync(0xFFFFFFFFu, s, o);
            if (lane >= o) s += t;
        }
        warp_sums[lane] = s;
    }
    __syncthreads();
    int block_excl = (wid > 0) ? warp_sums[wid - 1] : 0;
    int incl_block = incl + block_excl;
    int block_total = warp_sums[31];

    if (threadIdx.x == 0) {
        int prefix = 0;
        if (b > 0) {
            while (atomicAdd(&g_flag[b - 1], 0) == 0) { }
            __threadfence();
            prefix = g_scanval[b - 1];
        }
        g_scanval[b] = prefix + block_total;
        __threadfence();
        atomicExch(&g_flag[b], 1);
        s_prefix = prefix;
    }
    __syncthreads();

    if (i < N_NODE) {
        int excl = s_prefix + incl_block - v;
        g_rowptr[i] = excl;
        g_cur[i] = excl;                              // fill cursor
        float d = (v == 0) ? 1.0f : (float)v;
        g_dinv[i] = rsqrtf(d);
        g_cnt[i] = 0;                                 // restore zero invariant
    }
    if (i == 0) g_rowptr[N_NODE] = N_EDGE;
}

// Fill CSR: packed (col, ea*dinv[col]); dinv[row] folded into SpMM.
// Single atomic gives the slot; only one random read (dinv[col]).
__global__ void k_fill(const int* __restrict__ row, const int* __restrict__ col,
                       const float* __restrict__ ea) {
    int e = blockIdx.x * blockDim.x + threadIdx.x;
    if (e < 64) g_flag[e] = 0;                        // reset scan flags for next call
    if (e >= N_EDGE) return;
    int r = row[e];
    int c = col[e];
    float v = ea[e] * __ldg(&g_dinv[c]);
    int pos = atomicAdd(&g_cur[r], 1);
    g_epk[pos] = make_int2(c, __float_as_int(v));
}

// ---------------- SpMM inner step helper ----------------
__device__ __forceinline__ void acc_edge(const __half* __restrict__ xin, int c,
                                         int2 pk,
                                         float& a0, float& a1, float& a2, float& a3,
                                         float& a4, float& a5, float& a6, float& a7) {
    float v = __int_as_float(pk.y);
    uint4 raw = __ldg((const uint4*)(xin + (size_t)pk.x * D_FEAT + c));
    float2 f0 = __half22float2(*(__half2*)&raw.x);
    float2 f1 = __half22float2(*(__half2*)&raw.y);
    float2 f2 = __half22float2(*(__half2*)&raw.z);
    float2 f3 = __half22float2(*(__half2*)&raw.w);
    a0 = fmaf(v, f0.x, a0); a1 = fmaf(v, f0.y, a1);
    a2 = fmaf(v, f1.x, a2); a3 = fmaf(v, f1.y, a3);
    a4 = fmaf(v, f2.x, a4); a5 = fmaf(v, f2.y, a5);
    a6 = fmaf(v, f3.x, a6); a7 = fmaf(v, f3.y, a7);
}

// ---------------- CSR SpMM: 8 threads per node, 8 feats each, MLP=4 ----------------
__global__ void __launch_bounds__(256) k_spmm(const __half* __restrict__ xin,
                                              float* __restrict__ y32,
                                              __half* __restrict__ y16) {
    int t = blockIdx.x * blockDim.x + threadIdx.x;
    int n = t >> 3;
    if (n >= N_NODE) return;
    int c = (t & 7) << 3;
    int s = __ldg(&g_rowptr[n]);
    int e = __ldg(&g_rowptr[n + 1]);

    float a0 = 0.f, a1 = 0.f, a2 = 0.f, a3 = 0.f;
    float a4 = 0.f, a5 = 0.f, a6 = 0.f, a7 = 0.f;

    int i = s;
    for (; i + 4 <= e; i += 4) {
        int2 p0 = __ldg(&g_epk[i]);
        int2 p1 = __ldg(&g_epk[i + 1]);
        int2 p2 = __ldg(&g_epk[i + 2]);
        int2 p3 = __ldg(&g_epk[i + 3]);
        const __half* b0 = xin + (size_t)p0.x * D_FEAT + c;
        const __half* b1 = xin + (size_t)p1.x * D_FEAT + c;
        const __half* b2 = xin + (size_t)p2.x * D_FEAT + c;
        const __half* b3 = xin + (size_t)p3.x * D_FEAT + c;
        uint4 r0 = __ldg((const uint4*)b0);
        uint4 r1 = __ldg((const uint4*)b1);
        uint4 r2 = __ldg((const uint4*)b2);
        uint4 r3 = __ldg((const uint4*)b3);
        float v0 = __int_as_float(p0.y), v1 = __int_as_float(p1.y);
        float v2 = __int_as_float(p2.y), v3 = __int_as_float(p3.y);
#define ACCUM(vv, rr)                                                   \
        {                                                               \
            float2 f0 = __half22float2(*(__half2*)&rr.x);               \
            float2 f1 = __half22float2(*(__half2*)&rr.y);               \
            float2 f2 = __half22float2(*(__half2*)&rr.z);               \
            float2 f3 = __half22float2(*(__half2*)&rr.w);               \
            a0 = fmaf(vv, f0.x, a0); a1 = fmaf(vv, f0.y, a1);           \
            a2 = fmaf(vv, f1.x, a2); a3 = fmaf(vv, f1.y, a3);           \
            a4 = fmaf(vv, f2.x, a4); a5 = fmaf(vv, f2.y, a5);           \
            a6 = fmaf(vv, f3.x, a6); a7 = fmaf(vv, f3.y, a7);           \
        }
        ACCUM(v0, r0); ACCUM(v1, r1); ACCUM(v2, r2); ACCUM(v3, r3);
    }
    for (; i < e; i++)
        acc_edge(xin, c, __ldg(&g_epk[i]), a0, a1, a2, a3, a4, a5, a6, a7);

    float dn = __ldg(&g_dinv[n]);           // fold dinv[row] here
    a0 *= dn; a1 *= dn; a2 *= dn; a3 *= dn;
    a4 *= dn; a5 *= dn; a6 *= dn; a7 *= dn;

    size_t off = (size_t)n * D_FEAT + c;
    *(float4*)(y32 + off)     = make_float4(a0, a1, a2, a3);
    *(float4*)(y32 + off + 4) = make_float4(a4, a5, a6, a7);

    __half2 o0 = __floats2half2_rn(a0, a1);
    __half2 o1 = __floats2half2_rn(a2, a3);
    __half2 o2 = __floats2half2_rn(a4, a5);
    __half2 o3 = __floats2half2_rn(a6, a7);
    *(uint4*)(y16 + off) = make_uint4(*(uint32_t*)&o0, *(uint32_t*)&o1,
                                      *(uint32_t*)&o2, *(uint32_t*)&o3);
}

// ---------------- fused SpMM3 + epilogue (same MLP=4 loop) ----------------
__global__ void __launch_bounds__(256) k_spmm_out(const __half* __restrict__ y2h,
                                                  const float* __restrict__ x,
                                                  float* __restrict__ out) {
    int t = blockIdx.x * blockDim.x + threadIdx.x;
    int n = t >> 3;
    if (n >= N_NODE) return;
    int c = (t & 7) << 3;
    int s = __ldg(&g_rowptr[n]);
    int e = __ldg(&g_rowptr[n + 1]);

    float a0 = 0.f, a1 = 0.f, a2 = 0.f, a3 = 0.f;
    float a4 = 0.f, a5 = 0.f, a6 = 0.f, a7 = 0.f;

    int i = s;
    for (; i + 4 <= e; i += 4) {
        int2 p0 = __ldg(&g_epk[i]);
        int2 p1 = __ldg(&g_epk[i + 1]);
        int2 p2 = __ldg(&g_epk[i + 2]);
        int2 p3 = __ldg(&g_epk[i + 3]);
        uint4 r0 = __ldg((const uint4*)(y2h + (size_t)p0.x * D_FEAT + c));
        uint4 r1 = __ldg((const uint4*)(y2h + (size_t)p1.x * D_FEAT + c));
        uint4 r2 = __ldg((const uint4*)(y2h + (size_t)p2.x * D_FEAT + c));
        uint4 r3 = __ldg((const uint4*)(y2h + (size_t)p3.x * D_FEAT + c));
        float v0 = __int_as_float(p0.y), v1 = __int_as_float(p1.y);
        float v2 = __int_as_float(p2.y), v3 = __int_as_float(p3.y);
        ACCUM(v0, r0); ACCUM(v1, r1); ACCUM(v2, r2); ACCUM(v3, r3);
    }
    for (; i < e; i++)
        acc_edge(y2h, c, __ldg(&g_epk[i]), a0, a1, a2, a3, a4, a5, a6, a7);

    float dn = __ldg(&g_dinv[n]);
    a0 *= dn; a1 *= dn; a2 *= dn; a3 *= dn;
    a4 *= dn; a5 *= dn; a6 *= dn; a7 *= dn;

    size_t off = (size_t)n * D_FEAT + c;
    float4 x0 = __ldg((const float4*)(x + off));
    float4 x1 = __ldg((const float4*)(x + off + 4));
    float4 p0 = *(const float4*)(g_y32 + off);
    float4 p1 = *(const float4*)(g_y32 + off + 4);
    float4 q0 = *(const float4*)(g_y32 + (size_t)NF + off);
    float4 q1 = *(const float4*)(g_y32 + (size_t)NF + off + 4);

    float* ob = out + (size_t)n * ((DEPTH + 1) * D_FEAT) + c;
#pragma unroll
    for (int L = 0; L <= DEPTH; L++) {
        float c0 = g_C[L * 4 + 0], c1 = g_C[L * 4 + 1];
        float c2 = g_C[L * 4 + 2], c3 = g_C[L * 4 + 3];
        float4 o;
        o.x = c0 * x0.x + c1 * p0.x + c2 * q0.x + c3 * a0;
        o.y = c0 * x0.y + c1 * p0.y + c2 * q0.y + c3 * a1;
        o.z = c0 * x0.z + c1 * p0.z + c2 * q0.z + c3 * a2;
        o.w = c0 * x0.w + c1 * p0.w + c2 * q0.w + c3 * a3;
        *(float4*)(ob + (size_t)L * D_FEAT) = o;
        float4 u;
        u.x = c0 * x1.x + c1 * p1.x + c2 * q1.x + c3 * a4;
        u.y = c0 * x1.y + c1 * p1.y + c2 * q1.y + c3 * a5;
        u.z = c0 * x1.z + c1 * p1.z + c2 * q1.z + c3 * a6;
        u.w = c0 * x1.w + c1 * p1.w + c2 * q1.w + c3 * a7;
        *(float4*)(ob + (size_t)L * D_FEAT + 4) = u;
    }
}

// ---------------- coefficient collapse (tiny, fp32) ----------------
__global__ void k_coef(const float* __restrict__ alphas, const float* __restrict__ w,
                       const float* __restrict__ aarr, const float* __restrict__ barr) {
    if (blockIdx.x != 0 || threadIdx.x != 0) return;
    const float l = -1.0f, r = 1.0f;
    float C[DEPTH + 1][DEPTH + 1];
    for (int L = 0; L <= DEPTH; L++)
        for (int k = 0; k <= DEPTH; k++) C[L][k] = 0.0f;

    for (int m = 0; m < M_TERMS; m++) {
        float a = aarr[m], b = barr[m], wm = w[m];
        float P[DEPTH + 1][DEPTH + 1];
        for (int L = 0; L <= DEPTH; L++)
            for (int k = 0; k <= DEPTH; k++) P[L][k] = 0.0f;
        P[0][0] = 1.0f;

        float coef1 = (a - b) * 0.5f - (a + b + 2.0f) * 0.5f * (l + r) / (r - l);
        float coef2 = (a + b + 2.0f) / (r - l);
        float al0 = alphas[0 * M_TERMS + m];
        P[1][0] = al0 * coef1;
        P[1][1] = al0 * coef2;

        for (int L = 2; L <= DEPTH; L++) {
            float Lf = (float)L;
            float coef_l     = 2.0f * Lf * (Lf + a + b) * (2.0f * Lf - 2.0f + a + b);
            float coef_lm1_1 = (2.0f * Lf + a + b - 1.0f) * (2.0f * Lf + a + b) * (2.0f * Lf + a + b - 2.0f);
            float coef_lm1_2 = (2.0f * Lf + a + b - 1.0f) * (a * a - b * b);
            float coef_lm2   = 2.0f * (Lf - 1.0f + a) * (Lf - 1.0f + b) * (2.0f * Lf + a + b);
            float alL   = alphas[(L - 1) * M_TERMS + m];
            float alLm1 = alphas[(L - 2) * M_TERMS + m];
            float t1 = alL * (coef_lm1_1 / coef_l);
            float t2 = alL * (coef_lm1_2 / coef_l);
            float t3 = alL * alLm1 * (coef_lm2 / coef_l);
            float t1_2 = t1 * (2.0f / (r - l));
            float t2_2 = t1 * ((r + l) / (r - l)) + t2;
            for (int k = 0; k <= L; k++) {
                float pm1 = (k > 0) ? P[L - 1][k - 1] : 0.0f;
                P[L][k] = t1_2 * pm1 - t2_2 * P[L - 1][k] - t3 * P[L - 2][k];
            }
        }
        for (int L = 0; L <= DEPTH; L++)
            for (int k = 0; k <= L; k++) C[L][k] += wm * P[L][k];
    }
    for (int L = 0; L <= DEPTH; L++)
        for (int k = 0; k <= DEPTH; k++) g_C[L * 4 + k] = C[L][k];
}

// ---------------- launch ----------------
extern "C" void kernel_launch(void* const* d_in, const int* in_sizes, int n_in,
                              void* d_out, int out_size) {
    const float* x      = (const float*)d_in[0];
    const int*   eidx   = (const int*)d_in[1];      // (2, N_EDGE): row then col
    const float* eattr  = (const float*)d_in[2];
    const float* alphas = (const float*)d_in[3];
    const float* w      = (const float*)d_in[4];
    const float* a_arr  = (const float*)d_in[5];
    const float* b_arr  = (const float*)d_in[6];
    float* out = (float*)d_out;

    const int* row = eidx;
    const int* col = eidx + N_EDGE;

    static float*  y32 = nullptr;
    static __half* yh  = nullptr;
    static __half* xh  = nullptr;
    if (!y32) {
        cudaGetSymbolAddress((void**)&y32, g_y32);
        cudaGetSymbolAddress((void**)&yh,  g_yh);
        cudaGetSymbolAddress((void**)&xh,  g_xh);
    }

    const int B = 256;
    k_deg_xtoh<<<(N_EDGE + B - 1) / B, B>>>(row, x);
    k_scan<<<NBLK_SCAN, SCAN_BS>>>();
    k_fill<<<(N_EDGE + B - 1) / B, B>>>(row, col, eattr);
    k_coef<<<1, 32>>>(alphas, w, a_arr, b_arr);

    const int spmm_blocks = (N_NODE * 8 + B - 1) / B;   // 1563
    k_spmm<<<spmm_blocks, B>>>(xh, y32,      yh);
    k_spmm<<<spmm_blocks, B>>>(yh, y32 + NF, yh + NF);
    k_spmm_out<<<spmm_blocks, B>>>(yh + NF, x, out);
}